// round 10
// baseline (speedup 1.0000x reference)
#include <cuda_runtime.h>

#define CH 6
#define MODES 16
#define BB 32
#define NPT 65536
#define NMASK 65535
#define TSTEPS 8

#define EXT 1026                 // logical window: indices 0..1025
#define SROW 1032                // padded row stride (float4 alignment)
#define VMARG 29                 // validity margin after 28 stage-shrinks (+1 end)
#define CORE 968                 // EXT - 2*VMARG, valid output core [29, 997)
#define NBLK 68                  // 68*968 = 65824 >= NPT
#define RKTHREADS 256            // 4 points/thread tile [1,1025) exactly
#define EDG 260                  // per-channel stride in edge arrays
#define FBLK 8                   // blocks per (b,i) in forward DFT

// -------- scratch (no allocations allowed) --------
__device__ float g_bufA[BB*CH*NPT];
__device__ float g_part[BB*CH*FBLK*MODES*2];
__device__ float g_Z[BB*CH*MODES*2];
__device__ float g_U[CH*CH*6];     // staging for Winograd weights

__constant__ float c_U[CH*CH*6];   // U[co][ci][r] = (G w)[r]
__constant__ float c_b[CH];

__device__ __forceinline__ float htanh(float x){
    float y;
    asm("tanh.approx.f32 %0, %1;" : "=f"(y) : "f"(x));
    return y;
}

// U = G w  for F(4,3):  G = [1/4; -1/6*(1,1,1); (-1,1,-1)/6; (1/24,1/12,1/6); (1/24,-1/12,1/6); (0,0,1)]
__global__ void init_U_kernel(const float* __restrict__ conv_w){
    int i = threadIdx.x;
    if (i < CH*CH){
        float w0 = conv_w[i*3+0], w1 = conv_w[i*3+1], w2 = conv_w[i*3+2];
        g_U[i*6+0] = 0.25f*w0;
        g_U[i*6+1] = -(w0+w1+w2)*(1.f/6.f);
        g_U[i*6+2] = (w1-w0-w2)*(1.f/6.f);
        g_U[i*6+3] = w0*(1.f/24.f) + w1*(1.f/12.f) + w2*(1.f/6.f);
        g_U[i*6+4] = w0*(1.f/24.f) - w1*(1.f/12.f) + w2*(1.f/6.f);
        g_U[i*6+5] = w2;
    }
}

// ---------------- Winograd F(4,3) input transform ----------------
// V = B^T d,  B^T rows: [4,0,-5,0,1,0],[0,-4,-4,1,1,0],[0,4,-4,-1,1,0],
//                       [0,-2,-1,2,1,0],[0,2,-1,-2,1,0],[0,4,0,-5,0,1]
__device__ __forceinline__ void wino_in(float d0,float d1,float d2,float d3,
                                        float d4,float d5, float* V){
    float t1 = d1+d2, t2 = d1-d2, t3 = d3+d4, t4 = d4-d3;
    float s1 = d3-d1, s2 = d4-d2;
    V[0] = fmaf(-5.f, d2, fmaf(4.f, d0, d4));
    V[1] = fmaf(-4.f, t1, t3);
    V[2] = fmaf( 4.f, t2, t4);
    V[3] = fmaf( 2.f, s1, s2);
    V[4] = fmaf(-2.f, s1, s2);
    V[5] = fmaf(-5.f, d3, fmaf(4.f, d1, d5));
}

// ---------------- stage ----------------
// 4 points/thread (own p0+1..p0+4), window [p0,p0+5] = one F(4,3) tile.
// Linearity split: cu = conv(u)+bias (stage 0); stages 1-3: a = cu + cc*conv(k).
// Edge arrays (double-buffered, stride-1): eL[i]=k(4i) (i=0 sentinel),
// eR[i]=k(4i+1) (i=256 sentinel). Stages 1-3 read only edges/kr, not su.

template<int S>
__device__ __forceinline__ void stage(
    float (&cu)[CH][4],
    const float* __restrict__ eLr, const float* __restrict__ eRr,
    float* __restrict__ eLw, float* __restrict__ eRw,
    const float* __restrict__ su,
    float cc, float aw, int gofs, int tid, bool edge,
    float (&kr)[CH][4], float (&acc)[CH][4])
{
    const int p0 = 4*tid;
    float V[CH][6];

    if (S == 0){
        #pragma unroll
        for (int ci=0; ci<CH; ci++){
            const float* ru = su + ci*SROW + p0;
            float4 u0 = *(const float4*)ru;          // p0..p0+3 (aligned)
            float2 u1 = *(const float2*)(ru + 4);    // p0+4, p0+5
            wino_in(u0.x, u0.y, u0.z, u0.w, u1.x, u1.y, V[ci]);
        }
    } else {
        float xl[CH], xr[CH];
        #pragma unroll
        for (int ci=0; ci<CH; ci++){
            xl[ci] = eLr[ci*EDG + tid];
            xr[ci] = eRr[ci*EDG + tid + 1];
        }
        #pragma unroll
        for (int ci=0; ci<CH; ci++){
            float d0=xl[ci], d1=kr[ci][0], d2=kr[ci][1],
                  d3=kr[ci][2], d4=kr[ci][3], d5=xr[ci];
            if (edge){
                if ((unsigned)(gofs+p0+0) >= NPT) d0 = 0.f;
                if ((unsigned)(gofs+p0+1) >= NPT) d1 = 0.f;
                if ((unsigned)(gofs+p0+2) >= NPT) d2 = 0.f;
                if ((unsigned)(gofs+p0+3) >= NPT) d3 = 0.f;
                if ((unsigned)(gofs+p0+4) >= NPT) d4 = 0.f;
                if ((unsigned)(gofs+p0+5) >= NPT) d5 = 0.f;
            }
            wino_in(d0, d1, d2, d3, d4, d5, V[ci]);
        }
    }

    #pragma unroll
    for (int co=0; co<CH; co++){
        float m0=0.f, m1=0.f, m2=0.f, m3=0.f, m4=0.f, m5=0.f;
        #pragma unroll
        for (int ci=0; ci<CH; ci++){
            const float* Up = &c_U[(co*CH+ci)*6];
            m0 = fmaf(Up[0], V[ci][0], m0);
            m1 = fmaf(Up[1], V[ci][1], m1);
            m2 = fmaf(Up[2], V[ci][2], m2);
            m3 = fmaf(Up[3], V[ci][3], m3);
            m4 = fmaf(Up[4], V[ci][4], m4);
            m5 = fmaf(Up[5], V[ci][5], m5);
        }
        // A^T: o0=m0+m1+m2+m3+m4; o1=m1-m2+2(m3-m4); o2=m1+m2+4(m3+m4); o3=m1-m2+8(m3-m4)+m5
        float pp = m3+m4, qq = m3-m4, ss = m1+m2, tt = m1-m2;
        float o0 = m0 + ss + pp;
        float o1 = fmaf(2.f, qq, tt);
        float o2 = fmaf(4.f, pp, ss);
        float o3 = fmaf(8.f, qq, tt) + m5;

        float a0, a1, a2, a3;
        if (S == 0){
            const float bias = c_b[co];
            a0 = o0 + bias; a1 = o1 + bias; a2 = o2 + bias; a3 = o3 + bias;
            cu[co][0]=a0; cu[co][1]=a1; cu[co][2]=a2; cu[co][3]=a3;
        } else {
            a0 = fmaf(cc, o0, cu[co][0]);
            a1 = fmaf(cc, o1, cu[co][1]);
            a2 = fmaf(cc, o2, cu[co][2]);
            a3 = fmaf(cc, o3, cu[co][3]);
        }
        float k0 = htanh(a0), k1 = htanh(a1), k2 = htanh(a2), k3 = htanh(a3);
        kr[co][0]=k0; kr[co][1]=k1; kr[co][2]=k2; kr[co][3]=k3;
        acc[co][0] = fmaf(aw, k0, acc[co][0]);
        acc[co][1] = fmaf(aw, k1, acc[co][1]);
        acc[co][2] = fmaf(aw, k2, acc[co][2]);
        acc[co][3] = fmaf(aw, k3, acc[co][3]);
        if (S < 3){
            eLw[co*EDG + tid + 1] = k3;   // k(4t+4)
            eRw[co*EDG + tid]     = k0;   // k(4t+1)
        }
    }
    if (S < 3) __syncthreads();
}

// ---------------- fused 7-step RK4 kernel ----------------
__global__ void __launch_bounds__(RKTHREADS, 2)
rk4_fused(const float* __restrict__ src, float* __restrict__ dst,
          const float* __restrict__ t_span)
{
    extern __shared__ float sm[];
    float* s_su = sm;                      // CH*SROW
    float* s_eL = s_su + CH*SROW;          // 2*CH*EDG
    float* s_eR = s_eL + 2*CH*EDG;         // 2*CH*EDG
    float* s_ts = s_eR + 2*CH*EDG;         // TSTEPS

    const int b    = blockIdx.y;
    const int bx   = blockIdx.x;
    const int gofs = bx*CORE - VMARG;
    const int tid  = threadIdx.x;
    const bool edge = (bx == 0) | (bx == gridDim.x - 1);
    const int p0 = 4*tid;

    if (tid < CH){
        s_eL[tid*EDG + 0] = 0.f;           // k(0) sentinels, both buffers
        s_eL[(CH+tid)*EDG + 0] = 0.f;
        s_eR[tid*EDG + 256] = 0.f;         // k(1025) sentinels, both buffers
        s_eR[(CH+tid)*EDG + 256] = 0.f;
    }
    if (tid < TSTEPS) s_ts[tid] = t_span[tid];
    #pragma unroll
    for (int ch=0; ch<CH; ch++){
        const float* sc = src + ((size_t)b*CH + ch)*NPT;
        for (int p=tid; p<EXT; p+=RKTHREADS){
            int g = gofs + p;
            s_su[ch*SROW + p] = ((unsigned)g < NPT) ? sc[g] : 0.f;
        }
    }
    __syncthreads();

    float* eL0 = s_eL;  float* eL1 = s_eL + CH*EDG;
    float* eR0 = s_eR;  float* eR1 = s_eR + CH*EDG;

    #pragma unroll 1
    for (int s=0; s<TSTEPS-1; s++){
        const float dt  = s_ts[s+1] - s_ts[s];
        const float hdt = 0.5f*dt;

        float cu[CH][4], kr[CH][4], acc[CH][4];
        #pragma unroll
        for (int co=0; co<CH; co++){
            acc[co][0]=0.f; acc[co][1]=0.f; acc[co][2]=0.f; acc[co][3]=0.f;
        }

        stage<0>(cu, eL0,eR0, eL0,eR0, s_su, 0.f, 1.f, gofs, tid, edge, kr, acc);
        stage<1>(cu, eL0,eR0, eL1,eR1, s_su, hdt, 2.f, gofs, tid, edge, kr, acc);
        stage<2>(cu, eL1,eR1, eL0,eR0, s_su, hdt, 2.f, gofs, tid, edge, kr, acc);
        stage<3>(cu, eL0,eR0, eL1,eR1, s_su, dt,  1.f, gofs, tid, edge, kr, acc);

        // su update fused into stage-3 epilogue (stages 1-3 never read su)
        const float dt6 = dt * (1.0f/6.0f);
        #pragma unroll
        for (int co=0; co<CH; co++){
            float* rp = s_su + co*SROW;
            #pragma unroll
            for (int j=0; j<4; j++){
                int p = p0 + 1 + j;
                int g = gofs + p;
                if (!edge || (unsigned)g < NPT)
                    rp[p] += dt6 * acc[co][j];
            }
        }
        __syncthreads();            // updated su visible to next step's stage 0
    }

    // final store: valid core [29, 997)
    #pragma unroll
    for (int co=0; co<CH; co++){
        float* dp = dst + ((size_t)b*CH + co)*NPT;
        const float* rp = s_su + co*SROW;
        #pragma unroll
        for (int j=0; j<4; j++){
            int p = p0 + 1 + j;
            int g = gofs + p;
            if (p >= VMARG && p < EXT-VMARG && (unsigned)g < NPT)
                dp[g] = rp[p];
        }
    }
}

// ---------------- forward 16-mode DFT (partial sums) ----------------
__global__ void __launch_bounds__(256)
fwd_dft_kernel(const float* __restrict__ u)
{
    const int blk  = blockIdx.x;                 // [0, BB*CH*FBLK)
    const int seg  = blk & (FBLK-1);
    const int bi   = blk / FBLK;                 // b*CH + i
    const int tid  = threadIdx.x;
    const int lane = tid & 31, warp = tid >> 5;
    const int n0   = seg*8192 + warp*1024 + lane;  // stride-32 walk, coalesced
    const float* x = u + (size_t)bi*NPT;

    const float TWO_PI = 6.283185307179586f;
    float cr[MODES], cim[MODES], ck[MODES], sk[MODES], dc[MODES], ds[MODES];
    #pragma unroll
    for (int k=0; k<MODES; k++){
        cr[k]=0.f; cim[k]=0.f;
        float a0 = TWO_PI * ((float)((k*n0) & NMASK) * (1.0f/NPT));
        sincosf(a0, &sk[k], &ck[k]);
        float ad = TWO_PI * ((float)(k*32) * (1.0f/NPT));
        sincosf(ad, &ds[k], &dc[k]);
    }
    #pragma unroll 2
    for (int j=0; j<32; j++){
        float v = __ldg(&x[n0 + (j<<5)]);
        #pragma unroll
        for (int k=0; k<MODES; k++){
            cr[k]  = fmaf( v, ck[k], cr[k]);     // X += u * e^{-i theta}
            cim[k] = fmaf(-v, sk[k], cim[k]);
            float nc = ck[k]*dc[k] - sk[k]*ds[k];
            sk[k] = fmaf(ck[k], ds[k], sk[k]*dc[k]);
            ck[k] = nc;
        }
    }
    #pragma unroll
    for (int k=0; k<MODES; k++){
        #pragma unroll
        for (int off=16; off; off>>=1){
            cr[k]  += __shfl_xor_sync(0xffffffffu, cr[k],  off);
            cim[k] += __shfl_xor_sync(0xffffffffu, cim[k], off);
        }
    }
    __shared__ float red[8][MODES*2];
    if (lane == 0){
        #pragma unroll
        for (int k=0; k<MODES; k++){
            red[warp][2*k]   = cr[k];
            red[warp][2*k+1] = cim[k];
        }
    }
    __syncthreads();
    if (tid < MODES*2){
        float s = 0.f;
        #pragma unroll
        for (int w=0; w<8; w++) s += red[w][tid];
        g_part[(bi*FBLK + seg)*(MODES*2) + tid] = s;
    }
}

// ---------------- mix: reduce partials, fold proj into mode weights ----------------
__global__ void mix_kernel(const float* __restrict__ sw_r, const float* __restrict__ sw_i,
                           const float* __restrict__ proj_w)
{
    const int b = blockIdx.x;
    const int t = threadIdx.x;         // 96 = CH*MODES
    const int o = t / MODES, k = t % MODES;
    float Zr = 0.f, Zi = 0.f;
    #pragma unroll
    for (int i=0; i<CH; i++){
        float Xr=0.f, Xi=0.f;
        int bi = b*CH + i;
        #pragma unroll
        for (int s=0; s<FBLK; s++){
            Xr += g_part[(bi*FBLK+s)*(MODES*2) + 2*k];
            Xi += g_part[(bi*FBLK+s)*(MODES*2) + 2*k + 1];
        }
        float Wr=0.f, Wi=0.f;
        #pragma unroll
        for (int c=0; c<CH; c++){
            float pw = proj_w[o*CH + c];
            Wr = fmaf(sw_r[(i*CH+c)*MODES + k], pw, Wr);
            Wi = fmaf(sw_i[(i*CH+c)*MODES + k], pw, Wi);
        }
        Zr += Xr*Wr - Xi*Wi;
        Zi += Xr*Wi + Xi*Wr;
    }
    float scale = (k==0) ? (1.0f/NPT) : (2.0f/NPT);   // irfft: DC once, others doubled
    g_Z[(b*CH+o)*MODES*2 + 2*k]     = Zr*scale;
    g_Z[(b*CH+o)*MODES*2 + 2*k + 1] = Zi*scale;
}

// ---------------- synthesis: 16-mode irfft + bias ----------------
__global__ void __launch_bounds__(256)
synth_kernel(float* __restrict__ out, const float* __restrict__ proj_b)
{
    const int blk  = blockIdx.x;        // b*8 + seg
    const int b    = blk >> 3, seg = blk & 7;
    const int tid  = threadIdx.x, lane = tid & 31, warp = tid >> 5;
    const int n0   = seg*8192 + warp*1024 + lane;

    __shared__ float zz[CH*MODES*2];
    __shared__ float pb[CH];
    if (tid < CH*MODES*2) zz[tid] = g_Z[b*CH*MODES*2 + tid];
    if (tid < CH)         pb[tid] = proj_b[tid];
    __syncthreads();

    const float TWO_PI = 6.283185307179586f;
    float ck[MODES], sk[MODES], dc[MODES], ds[MODES];
    #pragma unroll
    for (int k=0; k<MODES; k++){
        float a0 = TWO_PI * ((float)((k*n0) & NMASK) * (1.0f/NPT));
        sincosf(a0, &sk[k], &ck[k]);
        float ad = TWO_PI * ((float)(k*32) * (1.0f/NPT));
        sincosf(ad, &ds[k], &dc[k]);
    }
    for (int j=0; j<32; j++){
        int n = n0 + (j<<5);
        float accv[CH];
        #pragma unroll
        for (int o=0; o<CH; o++) accv[o] = pb[o];
        #pragma unroll
        for (int k=0; k<MODES; k++){
            float c = ck[k], s = sk[k];
            #pragma unroll
            for (int o=0; o<CH; o++){
                accv[o] = fmaf( zz[(o*MODES+k)*2],     c, accv[o]);
                accv[o] = fmaf(-zz[(o*MODES+k)*2 + 1], s, accv[o]);
            }
            float nc = c*dc[k] - s*ds[k];
            sk[k] = fmaf(c, ds[k], s*dc[k]);
            ck[k] = nc;
        }
        #pragma unroll
        for (int o=0; o<CH; o++)
            out[((size_t)(b*CH + o))*NPT + n] = accv[o];
    }
}

// ---------------- launch ----------------
extern "C" void kernel_launch(void* const* d_in, const int* in_sizes, int n_in,
                              void* d_out, int out_size)
{
    const float* u0     = (const float*)d_in[0];
    const float* t_span = (const float*)d_in[1];
    const float* conv_w = (const float*)d_in[2];
    const float* conv_b = (const float*)d_in[3];
    const float* sw_r   = (const float*)d_in[4];
    const float* sw_i   = (const float*)d_in[5];
    const float* proj_w = (const float*)d_in[6];
    const float* proj_b = (const float*)d_in[7];
    float* out = (float*)d_out;

    float* bufA = nullptr;
    float* Up   = nullptr;
    cudaGetSymbolAddress((void**)&bufA, g_bufA);
    cudaGetSymbolAddress((void**)&Up,   g_U);

    init_U_kernel<<<1, 64>>>(conv_w);
    cudaMemcpyToSymbolAsync(c_U, Up, CH*CH*6*sizeof(float), 0,
                            cudaMemcpyDeviceToDevice, 0);
    cudaMemcpyToSymbolAsync(c_b, conv_b, CH*sizeof(float), 0,
                            cudaMemcpyDeviceToDevice, 0);

    const int rk_smem = (CH*SROW + 4*CH*EDG + TSTEPS) * sizeof(float);
    cudaFuncSetAttribute(rk4_fused, cudaFuncAttributeMaxDynamicSharedMemorySize, rk_smem);

    dim3 rkgrid(NBLK, BB);
    rk4_fused<<<rkgrid, RKTHREADS, rk_smem>>>(u0, bufA, t_span);

    fwd_dft_kernel<<<BB*CH*FBLK, 256>>>(bufA);
    mix_kernel<<<BB, CH*MODES>>>(sw_r, sw_i, proj_w);
    synth_kernel<<<BB*8, 256>>>(out, proj_b);
}

// round 11
// speedup vs baseline: 2.0843x; 2.0843x over previous
#include <cuda_runtime.h>

#define CH 6
#define MODES 16
#define BB 32
#define NPT 65536
#define NMASK 65535
#define TSTEPS 8

#define EXT 1026                 // logical window: indices 0..1025
#define SROW 1032                // padded row stride (float4 alignment)
#define VMARG 29                 // validity margin after 28 stage-shrinks (+1 end)
#define CORE 968                 // EXT - 2*VMARG, valid output core [29, 997)
#define NBLK 68                  // 68*968 = 65824 >= NPT
#define RKTHREADS 256            // 4 points/thread tile [1,1025) exactly
#define EDG 260                  // per-channel stride in edge arrays
#define FBLK 8                   // blocks per (b,i) in forward DFT

// -------- scratch (no allocations allowed) --------
__device__ float g_bufA[BB*CH*NPT];
__device__ float g_part[BB*CH*FBLK*MODES*2];

__constant__ float c_w[CH*CH*3];   // [co][ci][3]
__constant__ float c_b[CH];

__device__ __forceinline__ float htanh(float x){
    float y;
    asm("tanh.approx.f32 %0, %1;" : "=f"(y) : "f"(x));
    return y;
}

// ---------------- stage (R9 proven version) ----------------
// 4 points/thread: own p0+1..p0+4 (p0=4*tid), window [p0, p0+5]; threads tile
// [1,1025) exactly — NO tail. Linearity split: cu = conv(u)+bias (stage 0);
// stages 1-3: a = cu + cc*conv(k). Edge arrays (double-buffered, stride-1):
//   eL[i] = k(4i)   (i=0 sentinel=0; thread t writes i=t+1 <- kr[3])
//   eR[i] = k(4i+1) (thread t writes i=t <- kr[0]; i=256 sentinel=0)
// Stages 1-3 read ONLY edges/kr (not su) -> su update needs no pre-barrier.

template<int S>
__device__ __forceinline__ void stage(
    float (&cu)[CH][4],
    const float* __restrict__ eLr, const float* __restrict__ eRr,
    float* __restrict__ eLw, float* __restrict__ eRw,
    const float* __restrict__ su,
    float cc, float aw, int gofs, int tid, bool edge,
    float (&kr)[CH][4], float (&acc)[CH][4])
{
    const int p0 = 4*tid;
    float a[CH][4];
    #pragma unroll
    for (int co=0; co<CH; co++){ a[co][0]=0.f; a[co][1]=0.f; a[co][2]=0.f; a[co][3]=0.f; }

    if (S == 0){
        #pragma unroll
        for (int ci=0; ci<CH; ci++){
            const float* ru = su + ci*SROW + p0;
            float4 u0 = *(const float4*)ru;          // p0..p0+3 (aligned)
            float2 u1 = *(const float2*)(ru + 4);    // p0+4, p0+5
            float xv[6] = {u0.x, u0.y, u0.z, u0.w, u1.x, u1.y};
            #pragma unroll
            for (int co=0; co<CH; co++){
                const float w0 = c_w[(co*CH+ci)*3 + 0];
                const float w1 = c_w[(co*CH+ci)*3 + 1];
                const float w2 = c_w[(co*CH+ci)*3 + 2];
                #pragma unroll
                for (int j=0; j<4; j++)
                    a[co][j] = fmaf(w0, xv[j], fmaf(w1, xv[j+1], fmaf(w2, xv[j+2], a[co][j])));
            }
        }
        // fold bias into cu
        #pragma unroll
        for (int co=0; co<CH; co++){
            const float bias = c_b[co];
            #pragma unroll
            for (int j=0; j<4; j++){
                a[co][j] += bias;
                cu[co][j] = a[co][j];
            }
        }
    } else {
        // hoisted, batched edge loads (MLP)
        float xl[CH], xr[CH];
        #pragma unroll
        for (int ci=0; ci<CH; ci++){
            xl[ci] = eLr[ci*EDG + tid];
            xr[ci] = eRr[ci*EDG + tid + 1];
        }
        #pragma unroll
        for (int ci=0; ci<CH; ci++){
            float xvk[6];
            xvk[0] = xl[ci];
            xvk[1] = kr[ci][0]; xvk[2] = kr[ci][1];
            xvk[3] = kr[ci][2]; xvk[4] = kr[ci][3];
            xvk[5] = xr[ci];
            if (edge){
                #pragma unroll
                for (int j=0; j<6; j++)
                    if ((unsigned)(gofs + p0 + j) >= NPT) xvk[j] = 0.f;
            }
            #pragma unroll
            for (int co=0; co<CH; co++){
                const float w0 = c_w[(co*CH+ci)*3 + 0];
                const float w1 = c_w[(co*CH+ci)*3 + 1];
                const float w2 = c_w[(co*CH+ci)*3 + 2];
                #pragma unroll
                for (int j=0; j<4; j++)
                    a[co][j] = fmaf(w0, xvk[j], fmaf(w1, xvk[j+1], fmaf(w2, xvk[j+2], a[co][j])));
            }
        }
        #pragma unroll
        for (int co=0; co<CH; co++)
            #pragma unroll
            for (int j=0; j<4; j++) a[co][j] = fmaf(cc, a[co][j], cu[co][j]);
    }

    #pragma unroll
    for (int co=0; co<CH; co++){
        #pragma unroll
        for (int j=0; j<4; j++){
            float t = htanh(a[co][j]);
            kr[co][j] = t;
            acc[co][j] = fmaf(aw, t, acc[co][j]);
        }
        if (S < 3){
            eLw[co*EDG + tid + 1] = kr[co][3];   // k(4t+4)
            eRw[co*EDG + tid]     = kr[co][0];   // k(4t+1)
        }
    }
    if (S < 3) __syncthreads();
}

// ---------------- fused 7-step RK4 kernel ----------------
__global__ void __launch_bounds__(RKTHREADS, 2)
rk4_fused(const float* __restrict__ src, float* __restrict__ dst,
          const float* __restrict__ t_span)
{
    extern __shared__ float sm[];
    float* s_su = sm;                      // CH*SROW
    float* s_eL = s_su + CH*SROW;          // 2*CH*EDG
    float* s_eR = s_eL + 2*CH*EDG;         // 2*CH*EDG
    float* s_ts = s_eR + 2*CH*EDG;         // TSTEPS

    const int b    = blockIdx.y;
    const int bx   = blockIdx.x;
    const int gofs = bx*CORE - VMARG;
    const int tid  = threadIdx.x;
    const bool edge = (bx == 0) | (bx == gridDim.x - 1);
    const int p0 = 4*tid;

    if (tid < CH){
        s_eL[tid*EDG + 0] = 0.f;           // k(0) sentinels, both buffers
        s_eL[(CH+tid)*EDG + 0] = 0.f;
        s_eR[tid*EDG + 256] = 0.f;         // k(1025) sentinels, both buffers
        s_eR[(CH+tid)*EDG + 256] = 0.f;
    }
    if (tid < TSTEPS) s_ts[tid] = t_span[tid];
    #pragma unroll
    for (int ch=0; ch<CH; ch++){
        const float* sc = src + ((size_t)b*CH + ch)*NPT;
        for (int p=tid; p<EXT; p+=RKTHREADS){
            int g = gofs + p;
            s_su[ch*SROW + p] = ((unsigned)g < NPT) ? sc[g] : 0.f;
        }
    }
    __syncthreads();

    float* eL0 = s_eL;  float* eL1 = s_eL + CH*EDG;
    float* eR0 = s_eR;  float* eR1 = s_eR + CH*EDG;

    #pragma unroll 1
    for (int s=0; s<TSTEPS-1; s++){
        const float dt  = s_ts[s+1] - s_ts[s];
        const float hdt = 0.5f*dt;

        float cu[CH][4], kr[CH][4], acc[CH][4];
        #pragma unroll
        for (int co=0; co<CH; co++){
            acc[co][0]=0.f; acc[co][1]=0.f; acc[co][2]=0.f; acc[co][3]=0.f;
        }

        stage<0>(cu, eL0,eR0, eL0,eR0, s_su, 0.f, 1.f, gofs, tid, edge, kr, acc);
        stage<1>(cu, eL0,eR0, eL1,eR1, s_su, hdt, 2.f, gofs, tid, edge, kr, acc);
        stage<2>(cu, eL1,eR1, eL0,eR0, s_su, hdt, 2.f, gofs, tid, edge, kr, acc);
        stage<3>(cu, eL0,eR0, eL1,eR1, s_su, dt,  1.f, gofs, tid, edge, kr, acc);

        // su update fused into stage-3 epilogue (stages 1-3 never read su)
        const float dt6 = dt * (1.0f/6.0f);
        #pragma unroll
        for (int co=0; co<CH; co++){
            float* rp = s_su + co*SROW;
            #pragma unroll
            for (int j=0; j<4; j++){
                int p = p0 + 1 + j;
                int g = gofs + p;
                if (!edge || (unsigned)g < NPT)
                    rp[p] += dt6 * acc[co][j];
            }
        }
        __syncthreads();            // updated su visible to next step's stage 0
    }

    // final store: valid core [29, 997)
    #pragma unroll
    for (int co=0; co<CH; co++){
        float* dp = dst + ((size_t)b*CH + co)*NPT;
        const float* rp = s_su + co*SROW;
        #pragma unroll
        for (int j=0; j<4; j++){
            int p = p0 + 1 + j;
            int g = gofs + p;
            if (p >= VMARG && p < EXT-VMARG && (unsigned)g < NPT)
                dp[g] = rp[p];
        }
    }
}

// ---------------- forward 16-mode DFT (partial sums) ----------------
__global__ void __launch_bounds__(256)
fwd_dft_kernel(const float* __restrict__ u)
{
    const int blk  = blockIdx.x;                 // [0, BB*CH*FBLK)
    const int seg  = blk & (FBLK-1);
    const int bi   = blk / FBLK;                 // b*CH + i
    const int tid  = threadIdx.x;
    const int lane = tid & 31, warp = tid >> 5;
    const int n0   = seg*8192 + warp*1024 + lane;  // stride-32 walk, coalesced
    const float* x = u + (size_t)bi*NPT;

    const float TWO_PI = 6.283185307179586f;
    float cr[MODES], cim[MODES], ck[MODES], sk[MODES], dc[MODES], ds[MODES];
    #pragma unroll
    for (int k=0; k<MODES; k++){
        cr[k]=0.f; cim[k]=0.f;
        float a0 = TWO_PI * ((float)((k*n0) & NMASK) * (1.0f/NPT));
        sincosf(a0, &sk[k], &ck[k]);
        float ad = TWO_PI * ((float)(k*32) * (1.0f/NPT));
        sincosf(ad, &ds[k], &dc[k]);
    }
    #pragma unroll 2
    for (int j=0; j<32; j++){
        float v = __ldg(&x[n0 + (j<<5)]);
        #pragma unroll
        for (int k=0; k<MODES; k++){
            cr[k]  = fmaf( v, ck[k], cr[k]);     // X += u * e^{-i theta}
            cim[k] = fmaf(-v, sk[k], cim[k]);
            float nc = ck[k]*dc[k] - sk[k]*ds[k];
            sk[k] = fmaf(ck[k], ds[k], sk[k]*dc[k]);
            ck[k] = nc;
        }
    }
    #pragma unroll
    for (int k=0; k<MODES; k++){
        #pragma unroll
        for (int off=16; off; off>>=1){
            cr[k]  += __shfl_xor_sync(0xffffffffu, cr[k],  off);
            cim[k] += __shfl_xor_sync(0xffffffffu, cim[k], off);
        }
    }
    __shared__ float red[8][MODES*2];
    if (lane == 0){
        #pragma unroll
        for (int k=0; k<MODES; k++){
            red[warp][2*k]   = cr[k];
            red[warp][2*k+1] = cim[k];
        }
    }
    __syncthreads();
    if (tid < MODES*2){
        float s = 0.f;
        #pragma unroll
        for (int w=0; w<8; w++) s += red[w][tid];
        g_part[(bi*FBLK + seg)*(MODES*2) + tid] = s;
    }
}

// ---------------- synthesis: fused mix + 16-mode irfft + bias ----------------
// Preamble (tid<96): recompute this batch's mode-mix from g_part (L2-resident)
// with proj folded in: Z[o][k] = scale * sum_i X[b,i,k] * (sum_c W[i,c,k] pw[o,c]).
__global__ void __launch_bounds__(256)
synth_kernel(float* __restrict__ out,
             const float* __restrict__ sw_r, const float* __restrict__ sw_i,
             const float* __restrict__ proj_w, const float* __restrict__ proj_b)
{
    const int blk  = blockIdx.x;        // b*8 + seg
    const int b    = blk >> 3, seg = blk & 7;
    const int tid  = threadIdx.x, lane = tid & 31, warp = tid >> 5;
    const int n0   = seg*8192 + warp*1024 + lane;

    __shared__ float zz[CH*MODES*2];
    __shared__ float pb[CH];
    if (tid < CH*MODES){
        const int o = tid / MODES, k = tid % MODES;
        float Zr = 0.f, Zi = 0.f;
        #pragma unroll
        for (int i=0; i<CH; i++){
            float Xr=0.f, Xi=0.f;
            int bi = b*CH + i;
            #pragma unroll
            for (int s=0; s<FBLK; s++){
                Xr += g_part[(bi*FBLK+s)*(MODES*2) + 2*k];
                Xi += g_part[(bi*FBLK+s)*(MODES*2) + 2*k + 1];
            }
            float Wr=0.f, Wi=0.f;
            #pragma unroll
            for (int c=0; c<CH; c++){
                float pw = proj_w[o*CH + c];
                Wr = fmaf(sw_r[(i*CH+c)*MODES + k], pw, Wr);
                Wi = fmaf(sw_i[(i*CH+c)*MODES + k], pw, Wi);
            }
            Zr += Xr*Wr - Xi*Wi;
            Zi += Xr*Wi + Xi*Wr;
        }
        float scale = (k==0) ? (1.0f/NPT) : (2.0f/NPT);   // irfft: DC once, others doubled
        zz[(o*MODES+k)*2]     = Zr*scale;
        zz[(o*MODES+k)*2 + 1] = Zi*scale;
    }
    if (tid < CH) pb[tid] = proj_b[tid];
    __syncthreads();

    const float TWO_PI = 6.283185307179586f;
    float ck[MODES], sk[MODES], dc[MODES], ds[MODES];
    #pragma unroll
    for (int k=0; k<MODES; k++){
        float a0 = TWO_PI * ((float)((k*n0) & NMASK) * (1.0f/NPT));
        sincosf(a0, &sk[k], &ck[k]);
        float ad = TWO_PI * ((float)(k*32) * (1.0f/NPT));
        sincosf(ad, &ds[k], &dc[k]);
    }
    for (int j=0; j<32; j++){
        int n = n0 + (j<<5);
        float accv[CH];
        #pragma unroll
        for (int o=0; o<CH; o++) accv[o] = pb[o];
        #pragma unroll
        for (int k=0; k<MODES; k++){
            float c = ck[k], s = sk[k];
            #pragma unroll
            for (int o=0; o<CH; o++){
                accv[o] = fmaf( zz[(o*MODES+k)*2],     c, accv[o]);
                accv[o] = fmaf(-zz[(o*MODES+k)*2 + 1], s, accv[o]);
            }
            float nc = c*dc[k] - s*ds[k];
            sk[k] = fmaf(c, ds[k], s*dc[k]);
            ck[k] = nc;
        }
        #pragma unroll
        for (int o=0; o<CH; o++)
            out[((size_t)(b*CH + o))*NPT + n] = accv[o];
    }
}

// ---------------- launch ----------------
extern "C" void kernel_launch(void* const* d_in, const int* in_sizes, int n_in,
                              void* d_out, int out_size)
{
    const float* u0     = (const float*)d_in[0];
    const float* t_span = (const float*)d_in[1];
    const float* conv_w = (const float*)d_in[2];
    const float* conv_b = (const float*)d_in[3];
    const float* sw_r   = (const float*)d_in[4];
    const float* sw_i   = (const float*)d_in[5];
    const float* proj_w = (const float*)d_in[6];
    const float* proj_b = (const float*)d_in[7];
    float* out = (float*)d_out;

    float* bufA = nullptr;
    cudaGetSymbolAddress((void**)&bufA, g_bufA);

    cudaMemcpyToSymbolAsync(c_w, conv_w, CH*CH*3*sizeof(float), 0,
                            cudaMemcpyDeviceToDevice, 0);
    cudaMemcpyToSymbolAsync(c_b, conv_b, CH*sizeof(float), 0,
                            cudaMemcpyDeviceToDevice, 0);

    const int rk_smem = (CH*SROW + 4*CH*EDG + TSTEPS) * sizeof(float);
    cudaFuncSetAttribute(rk4_fused, cudaFuncAttributeMaxDynamicSharedMemorySize, rk_smem);

    dim3 rkgrid(NBLK, BB);
    rk4_fused<<<rkgrid, RKTHREADS, rk_smem>>>(u0, bufA, t_span);

    fwd_dft_kernel<<<BB*CH*FBLK, 256>>>(bufA);
    synth_kernel<<<BB*8, 256>>>(out, sw_r, sw_i, proj_w, proj_b);
}